// round 5
// baseline (speedup 1.0000x reference)
#include <cuda_runtime.h>
#include <cstdint>

// Scratch for selection results (no allocations allowed).
__device__ int   g_idx[64];
__device__ float g_w[64];

// ---------------------------------------------------------------------------
// Kernel 1: masked logit + iterative Gumbel top-k selection. One warp.
// N = 64 logits, each lane owns entries {lane, lane+32}.
// ---------------------------------------------------------------------------
__global__ void select_kernel(const float* __restrict__ logit,
                              const float* __restrict__ bg,
                              const float* __restrict__ gumbel,
                              float* __restrict__ out_logit,
                              const int* __restrict__ kptr,
                              int k_default) {
    const int lane = threadIdx.x;           // 0..31
    int k = kptr ? *kptr : k_default;
    if (k < 1 || k > 64) k = k_default;

    float ml0 = logit[lane]      + logf(fmaxf(1.0f - bg[lane],      1e-8f));
    float ml1 = logit[lane + 32] + logf(fmaxf(1.0f - bg[lane + 32], 1e-8f));
    out_logit[lane]      = ml0;
    out_logit[lane + 32] = ml1;

    float p0 = ml0 + gumbel[lane];
    float p1 = ml1 + gumbel[lane + 32];
    float m0 = 0.0f, m1 = 0.0f;

    for (int it = 0; it < k; ++it) {
        float v0 = p0 + m0;
        float v1 = p1 + m1;
        // local argmax, tie -> lower index
        float best = v0;
        int bi = lane;
        if (v1 > best) { best = v1; bi = lane + 32; }
        // warp argmax reduction, tie -> lower index
        #pragma unroll
        for (int off = 16; off > 0; off >>= 1) {
            float ob = __shfl_xor_sync(0xffffffffu, best, off);
            int   oi = __shfl_xor_sync(0xffffffffu, bi,   off);
            if (ob > best || (ob == best && oi < bi)) { best = ob; bi = oi; }
        }
        // softmax value at argmax: 1 / sum_j exp((v_j - best)/tau), tau = 0.01
        float s = expf((v0 - best) * 100.0f) + expf((v1 - best) * 100.0f);
        #pragma unroll
        for (int off = 16; off > 0; off >>= 1)
            s += __shfl_xor_sync(0xffffffffu, s, off);

        if (lane == 0) { g_idx[it] = bi; g_w[it] = 1.0f / s; }
        // mask out the selected entry
        if (bi == lane)      m0 += -1e9f;
        if (bi == lane + 32) m1 += -1e9f;
    }
}

// ---------------------------------------------------------------------------
// Kernel 2a: image gather, scaled by w_k.
// out[k][c][hp][wp][dp] = image[c][patch(k)] * w_k
// One float4 per thread; patch row = 16 contiguous float4 -> fully coalesced.
// Grid: 8*4*65536 / 256 = 8192 blocks.
// ---------------------------------------------------------------------------
__global__ void __launch_bounds__(256)
gather_img_kernel(const float* __restrict__ img,
                  float* __restrict__ out) {
    const unsigned i = blockIdx.x * blockDim.x + threadIdx.x;  // < 2^21
    int k   = i >> 18;                 // / (4*65536)
    int r   = i & ((4 << 16) - 1);
    int c   = r >> 16;
    int off = r & 65535;
    int dp4 = off & 15, wp = (off >> 4) & 63, hp = off >> 10;
    int n   = g_idx[k];
    int hn  = n >> 4, wn = (n >> 2) & 3, dn = n & 3;
    long src = (long)c * 16777216
             + (long)(hn * 64 + hp) * 65536
             + (long)(wn * 64 + wp) * 256
             + (long)(dn * 64 + dp4 * 4);
    float4 v = *(const float4*)(img + src);
    float w = g_w[k];
    v.x *= w; v.y *= w; v.z *= w; v.w *= w;
    ((float4*)out)[i] = v;
}

// ---------------------------------------------------------------------------
// Kernel 2b: label gather (unscaled; hard one-hot weight == 1).
// Grid: 8*65536 / 256 = 2048 blocks.
// ---------------------------------------------------------------------------
__global__ void __launch_bounds__(256)
gather_lab_kernel(const float* __restrict__ lab,
                  float* __restrict__ out) {
    const unsigned j = blockIdx.x * blockDim.x + threadIdx.x;  // < 2^19
    int k   = j >> 16;
    int off = j & 65535;
    int dp4 = off & 15, wp = (off >> 4) & 63, hp = off >> 10;
    int n   = g_idx[k];
    int hn  = n >> 4, wn = (n >> 2) & 3, dn = n & 3;
    long src = (long)(hn * 64 + hp) * 65536
             + (long)(wn * 64 + wp) * 256
             + (long)(dn * 64 + dp4 * 4);
    ((float4*)out)[j] = *(const float4*)(lab + src);
}

extern "C" void kernel_launch(void* const* d_in, const int* in_sizes, int n_in,
                              void* d_out, int out_size) {
    const float* image  = (const float*)d_in[0];   // [1,4,256,256,256]
    const float* label  = (const float*)d_in[1];   // [1,1,256,256,256]
    const float* logit  = (const float*)d_in[2];   // [1,1,4,4,4]
    const float* bg     = (const float*)d_in[3];   // [1,1,4,4,4]
    const float* gumbel = (const float*)d_in[4];   // [1,64]
    const int*   kptr   = (n_in >= 6) ? (const int*)d_in[5] : nullptr;

    float* out       = (float*)d_out;
    float* out_lab   = out + (long)8 * 4 * 262144;         // after img block
    float* out_logit = out_lab + (long)8 * 262144;         // after lab block

    select_kernel<<<1, 32>>>(logit, bg, gumbel, out_logit, kptr, 8);
    gather_img_kernel<<<8192, 256>>>(image, out);
    gather_lab_kernel<<<2048, 256>>>(label, out_lab);
}